// round 4
// baseline (speedup 1.0000x reference)
#include <cuda_runtime.h>
#include <cstdint>

// ---------------- problem constants ----------------
#define BB 8
#define TT 256
#define UU 64
#define JJ 512          // K dim
#define VV 300          // vocab
#define NP 320          // padded vocab (mult of 8)
#define NCHUNK 16       // K chunks of 32
#define NFRAG_B 160     // 40 n-tiles * 4 k-steps per chunk

// ---------------- scratch (device globals; no allocs allowed) ----------------
__device__ float g_enc_s[BB * TT * JJ];               // 4 MB   (enc projection)
__device__ float g_pred_s[BB * UU * JJ];              // 1 MB   (pred projection)
__device__ float g_wfrag[NCHUNK * NFRAG_B * 64];      // 640 KB (W_out, tf32, fragment-ready)

// ---------------- helpers ----------------
__device__ __forceinline__ uint32_t f2tf32(float x) {
    uint32_t r;
    asm("cvt.rna.tf32.f32 %0, %1;" : "=r"(r) : "f"(x));
    return r;
}

// accurate fast tanh: 2 MUFU (EX2 + RCP), rel err ~1e-6
__device__ __forceinline__ float fast_tanh(float x) {
    float e = __expf(2.0f * x);
    return 1.0f - __fdividef(2.0f, e + 1.0f);
}

__device__ __forceinline__ void mma_tf32(float* d, const uint32_t* a, const uint32_t* b) {
    asm volatile(
        "mma.sync.aligned.m16n8k8.row.col.f32.tf32.tf32.f32 "
        "{%0,%1,%2,%3}, {%4,%5,%6,%7}, {%8,%9}, {%0,%1,%2,%3};"
        : "+f"(d[0]), "+f"(d[1]), "+f"(d[2]), "+f"(d[3])
        : "r"(a[0]), "r"(a[1]), "r"(a[2]), "r"(a[3]), "r"(b[0]), "r"(b[1]));
}

// ---------------- kernel 1: W_out -> tf32 fragment-ready layout ----------------
// Layout: [chunk c][frag g = nt*4+ks][lane][h], h in {0,1}.
// Fragment value: b_h = W[n = nt*8 + lane/4][k = c*32 + ks*8 + lane%4 + 4h]  (0 if n >= 300)
__global__ void prep_wfrag_kernel(const float* __restrict__ W_out) {
    const int g = blockIdx.x;      // 0..159
    const int c = blockIdx.y;      // 0..15
    const int t = threadIdx.x;     // 0..63
    const int lane = t >> 1, h = t & 1;
    const int nt = g >> 2, ks = g & 3;
    const int n = nt * 8 + (lane >> 2);
    const int k = c * 32 + ks * 8 + (lane & 3) + 4 * h;
    float val = (n < VV) ? W_out[n * JJ + k] : 0.0f;
    g_wfrag[(c * NFRAG_B + g) * 64 + lane * 2 + h] = __uint_as_float(f2tf32(val));
}

// ---------------- kernel 2: enc/pred projections (fp32 FFMA tiled GEMM) ----------------
__global__ __launch_bounds__(256) void proj_kernel(
    const float* __restrict__ enc, const float* __restrict__ pred,
    const float* __restrict__ W_enc, const float* __restrict__ b_enc,
    const float* __restrict__ W_pred, const float* __restrict__ b_pred)
{
    __shared__ __align__(16) float As[16][68];
    __shared__ __align__(16) float Bs[16][68];

    const int z = blockIdx.z;
    const int bx = blockIdx.x, by = blockIdx.y;
    if (z == 1 && bx >= 8) return;

    const float* X    = z ? pred     : enc;
    const float* W    = z ? W_pred   : W_enc;
    const float* bias = z ? b_pred   : b_enc;
    float*       Y    = z ? g_pred_s : g_enc_s;

    const int tid = threadIdx.x;
    const int m0 = bx * 64, n0 = by * 64;
    const int r  = tid >> 2, qq = tid & 3;
    const int tx = tid & 15, ty = tid >> 4;

    float acc[4][4] = {};

    for (int k0 = 0; k0 < JJ; k0 += 16) {
        float4 a4 = *(const float4*)(X + (size_t)(m0 + r) * JJ + k0 + qq * 4);
        float4 w4 = *(const float4*)(W + (size_t)(n0 + r) * JJ + k0 + qq * 4);
        __syncthreads();
        As[qq * 4 + 0][r] = a4.x; As[qq * 4 + 1][r] = a4.y;
        As[qq * 4 + 2][r] = a4.z; As[qq * 4 + 3][r] = a4.w;
        Bs[qq * 4 + 0][r] = w4.x; Bs[qq * 4 + 1][r] = w4.y;
        Bs[qq * 4 + 2][r] = w4.z; Bs[qq * 4 + 3][r] = w4.w;
        __syncthreads();
        #pragma unroll
        for (int d = 0; d < 16; d++) {
            float4 av = *(const float4*)&As[d][ty * 4];
            float4 bv = *(const float4*)&Bs[d][tx * 4];
            float a[4]  = {av.x, av.y, av.z, av.w};
            float bb[4] = {bv.x, bv.y, bv.z, bv.w};
            #pragma unroll
            for (int i = 0; i < 4; i++)
                #pragma unroll
                for (int j = 0; j < 4; j++)
                    acc[i][j] += a[i] * bb[j];
        }
    }

    float4 bia = *(const float4*)(bias + n0 + tx * 4);
    float bb[4] = {bia.x, bia.y, bia.z, bia.w};
    #pragma unroll
    for (int i = 0; i < 4; i++) {
        float4 o;
        o.x = acc[i][0] + bb[0]; o.y = acc[i][1] + bb[1];
        o.z = acc[i][2] + bb[2]; o.w = acc[i][3] + bb[3];
        *(float4*)(Y + (size_t)(m0 + ty * 4 + i) * JJ + n0 + tx * 4) = o;
    }
}

// ---------------- kernel 3: fused tanh-joint + vocab GEMM (mma.sync tf32) ----------------
// Grid: 1024 CTAs = (b, t-pair). CTA tile: M=128 (2t x 64u) x N=320(pad) x K=512.
// 512 threads = 16 warps, warp grid 4Mx4N, warp tile 32x80.
// SMEM: bias[320] | A stages 2x16KB (32 frags x 32 lanes x 16B) | B stages 2x40KB (160 frags x 32 x 8B)
static constexpr int OFF_BIAS = 0;
static constexpr int OFF_A    = 2048;
static constexpr int A_STRIDE = 16384;
static constexpr int OFF_B    = 2048 + 2 * 16384;     // 34816
static constexpr int B_STRIDE = 40960;
static constexpr int JK_SMEM  = OFF_B + 2 * B_STRIDE; // 116736

__global__ __launch_bounds__(512, 1) void joint_kernel(const float* __restrict__ b_out,
                                                       float* __restrict__ out)
{
    extern __shared__ char smem[];
    const int tid  = threadIdx.x;
    const int wid  = tid >> 5;
    const int lane = tid & 31;
    const int b    = blockIdx.x >> 7;
    const int t0   = (blockIdx.x & 127) * 2;

    const int warp_m = wid >> 2;      // 0..3 -> rows  warp_m*32 .. +32
    const int warp_n = wid & 3;       // 0..3 -> cols  warp_n*80 .. +80
    const int ntbase = warp_n * 10;
    const int mt0 = warp_m * 2, mt1 = warp_m * 2 + 1;

    float* bias_sm = (float*)(smem + OFF_BIAS);
    for (int i = tid; i < NP; i += 512) bias_sm[i] = (i < VV) ? b_out[i] : 0.0f;

    const float* __restrict__ encR0 = g_enc_s + (size_t)(b * TT + t0) * JJ;
    const float* __restrict__ predB = g_pred_s + (size_t)b * UU * JJ;

    float acc[2][10][4];
    #pragma unroll
    for (int i = 0; i < 2; i++)
        #pragma unroll
        for (int j = 0; j < 10; j++)
            #pragma unroll
            for (int k = 0; k < 4; k++) acc[i][j][k] = 0.0f;

    // -------- producer lambda-equivalent (macro-free, inlined twice) --------
    // A fragment-ready fill: thread handles frag-lanes fl = tid, tid+512.
    //   f = fl>>5 (mt*4+ks), lane_f = fl&31; r = lane_f>>2, q = lane_f&3
    //   m0r = mt*16+r, m1r = m0r+8 (same tl block); c0 = k0+ks*8+q, c1 = c0+4
    //   a0=tanh(e0+p(u0,c0)) a1=tanh(e0+p(u1,c0)) a2=tanh(e1+p(u0,c1)) a3=tanh(e1+p(u1,c1))
    #define PRODUCE(cc, bufp)  do {                                                   \
        const int k0p = (cc) * 32;                                                    \
        char* Abuf = smem + OFF_A + (bufp) * A_STRIDE;                                \
        _Pragma("unroll")                                                             \
        for (int ii = 0; ii < 2; ii++) {                                              \
            int fl = tid + ii * 512;                                                  \
            int f = fl >> 5, lf = fl & 31;                                            \
            int mt = f >> 2, ks = f & 3;                                              \
            int rr = lf >> 2, qf = lf & 3;                                            \
            int mrow = mt * 16 + rr;                                                  \
            int tl = mrow >> 6;                                                       \
            int u0 = mrow & 63, u1 = u0 + 8;                                          \
            int c0 = k0p + ks * 8 + qf, c1 = c0 + 4;                                  \
            float e0 = encR0[(size_t)tl * JJ + c0];                                   \
            float e1 = encR0[(size_t)tl * JJ + c1];                                   \
            float p00 = predB[(size_t)u0 * JJ + c0];                                  \
            float p01 = predB[(size_t)u0 * JJ + c1];                                  \
            float p10 = predB[(size_t)u1 * JJ + c0];                                  \
            float p11 = predB[(size_t)u1 * JJ + c1];                                  \
            uint4 fr;                                                                 \
            fr.x = f2tf32(fast_tanh(e0 + p00));                                       \
            fr.y = f2tf32(fast_tanh(e0 + p10));                                       \
            fr.z = f2tf32(fast_tanh(e1 + p01));                                       \
            fr.w = f2tf32(fast_tanh(e1 + p11));                                       \
            *(uint4*)(Abuf + f * 512 + lf * 16) = fr;                                 \
        }                                                                             \
        const float4* wsrc = (const float4*)(g_wfrag + (size_t)(cc) * NFRAG_B * 64);  \
        float4* wdst = (float4*)(smem + OFF_B + (bufp) * B_STRIDE);                   \
        _Pragma("unroll")                                                             \
        for (int ii = 0; ii < 5; ii++) wdst[tid + ii * 512] = wsrc[tid + ii * 512];   \
    } while (0)

    PRODUCE(0, 0);
    __syncthreads();

    #pragma unroll 1
    for (int c = 0; c < NCHUNK; c++) {
        const int buf = c & 1;
        if (c + 1 < NCHUNK) { PRODUCE(c + 1, buf ^ 1); }

        const char* Abuf = smem + OFF_A + buf * A_STRIDE;
        const char* Bbuf = smem + OFF_B + buf * B_STRIDE;
        #pragma unroll
        for (int ks = 0; ks < 4; ks++) {
            uint4 af0 = *(const uint4*)(Abuf + (mt0 * 4 + ks) * 512 + lane * 16);
            uint4 af1 = *(const uint4*)(Abuf + (mt1 * 4 + ks) * 512 + lane * 16);
            const uint32_t a0[4] = {af0.x, af0.y, af0.z, af0.w};
            const uint32_t a1[4] = {af1.x, af1.y, af1.z, af1.w};
            #pragma unroll
            for (int nt = 0; nt < 10; nt++) {
                uint2 bf = *(const uint2*)(Bbuf + ((ntbase + nt) * 4 + ks) * 256 + lane * 8);
                const uint32_t bv[2] = {bf.x, bf.y};
                mma_tf32(acc[0][nt], a0, bv);
                mma_tf32(acc[1][nt], a1, bv);
            }
        }
        __syncthreads();
    }

    // -------- epilogue: bias add + guarded float2 stores --------
    {
        const int rr = lane >> 2, qf = lane & 3;
        #pragma unroll
        for (int i = 0; i < 2; i++) {
            const int mbase = warp_m * 32 + i * 16 + rr;
            #pragma unroll
            for (int half = 0; half < 2; half++) {
                const int m = mbase + half * 8;
                const int tl = m >> 6, u = m & 63;
                float* orow = out + (size_t)((b * TT + t0 + tl) * UU + u) * VV;
                #pragma unroll
                for (int nt = 0; nt < 10; nt++) {
                    const int n0 = warp_n * 80 + nt * 8 + 2 * qf;
                    if (n0 < VV) {
                        float2 o;
                        o.x = acc[i][nt][half * 2 + 0] + bias_sm[n0];
                        o.y = acc[i][nt][half * 2 + 1] + bias_sm[n0 + 1];
                        *(float2*)(orow + n0) = o;
                    }
                }
            }
        }
    }
    #undef PRODUCE
}

// ---------------- launch ----------------
extern "C" void kernel_launch(void* const* d_in, const int* in_sizes, int n_in,
                              void* d_out, int out_size) {
    const float* enc    = (const float*)d_in[0];
    const float* pred   = (const float*)d_in[1];
    const float* W_enc  = (const float*)d_in[2];
    const float* b_enc  = (const float*)d_in[3];
    const float* W_pred = (const float*)d_in[4];
    const float* b_pred = (const float*)d_in[5];
    const float* W_out  = (const float*)d_in[6];
    const float* b_out  = (const float*)d_in[7];
    float* out = (float*)d_out;

    cudaFuncSetAttribute(joint_kernel, cudaFuncAttributeMaxDynamicSharedMemorySize, JK_SMEM);

    prep_wfrag_kernel<<<dim3(NFRAG_B, NCHUNK), 64>>>(W_out);
    proj_kernel<<<dim3(32, 8, 2), 256>>>(enc, pred, W_enc, b_enc, W_pred, b_pred);
    joint_kernel<<<BB * (TT / 2), 512, JK_SMEM>>>(b_out, out);
}